// round 11
// baseline (speedup 1.0000x reference)
#include <cuda_runtime.h>
#include <cuda_bf16.h>
#include <cstdint>

// ---------------------------------------------------------------------------
// GCN5 — R10: 16B bf16 gathers in k_agg (LDG-issue bound -> halve LDG count),
// W transpose/tf32 fused into GEMM staging, dinv fused into scan1, cnorm
// computed on the fly (no g_cnorm array).
//   Tb = bf16(H @ W)    (128-node tile, 8 warps, m16n8k8 tf32 MMA)
//   H  = relu(dinv^2*Tb + sum_in dinv[s]*dinv[d]*Tb[s] + b)   (fp32 accum)
// ---------------------------------------------------------------------------

#define MAXN 100000
#define MAXE 1600000
#define MAXF 128
#define NGRAPH 64
#define SCAN_BLK 256

__device__ __align__(16) __nv_bfloat16 g_Tb[MAXN * MAXF];  // post-GEMM (bf16)
__device__ float g_H[MAXN * MAXF];       // activations (fp32)
__device__ float g_dinv[MAXN];
__device__ int   g_cnt_i[MAXN];
__device__ int   g_rowptr[MAXN + 1];
__device__ int   g_cursor[MAXN];
__device__ int   g_csrc[MAXE];
__device__ int   g_bsum[512];
__device__ float g_pool[NGRAPH * 32];
__device__ float g_cnt[NGRAPH];

__device__ __forceinline__ uint32_t f2tf32(float f) {
    uint32_t r;
    asm("cvt.rna.tf32.f32 %0, %1;" : "=r"(r) : "f"(f));
    return r;
}

// ---------------- CSR build ----------------
__global__ void k_zero_cnt(int N) {
    int i = blockIdx.x * blockDim.x + threadIdx.x;
    if (i < N) g_cnt_i[i] = 0;
}
__global__ void k_count(const int* __restrict__ ei, int E) {
    int e = blockIdx.x * blockDim.x + threadIdx.x;
    if (e < E) atomicAdd(&g_cnt_i[ei[E + e]], 1);
}
// scan1 also computes dinv (deg = cnt + 1 self loop) and zeroes cursors.
__global__ void k_scan1(int N) {
    __shared__ int sh[SCAN_BLK];
    int tid = threadIdx.x;
    int i = blockIdx.x * SCAN_BLK + tid;
    int cnt = (i < N) ? g_cnt_i[i] : 0;
    if (i < N) {
        g_dinv[i] = rsqrtf((float)cnt + 1.0f);
        g_cursor[i] = 0;
    }
    sh[tid] = cnt;
    __syncthreads();
#pragma unroll
    for (int o = 1; o < SCAN_BLK; o <<= 1) {
        int t = (tid >= o) ? sh[tid - o] : 0;
        __syncthreads();
        sh[tid] += t;
        __syncthreads();
    }
    if (i < N) g_rowptr[i + 1] = sh[tid];
    if (tid == SCAN_BLK - 1) g_bsum[blockIdx.x] = sh[tid];
}
__global__ void k_scan2(int nb) {
    __shared__ int sh[512];
    int tid = threadIdx.x;
    sh[tid] = (tid < nb) ? g_bsum[tid] : 0;
    __syncthreads();
#pragma unroll
    for (int o = 1; o < 512; o <<= 1) {
        int t = (tid >= o) ? sh[tid - o] : 0;
        __syncthreads();
        sh[tid] += t;
        __syncthreads();
    }
    if (tid < nb) g_bsum[tid] = sh[tid];
}
__global__ void k_scan3(int N) {
    int i = blockIdx.x * SCAN_BLK + threadIdx.x;
    if (i < N && blockIdx.x > 0) g_rowptr[i + 1] += g_bsum[blockIdx.x - 1];
    if (i == 0) g_rowptr[0] = 0;
}
__global__ void k_fill(const int* __restrict__ ei, int E) {
    int e = blockIdx.x * blockDim.x + threadIdx.x;
    if (e >= E) return;
    int s = ei[e];
    int d = ei[E + e];
    int pos = atomicAdd(&g_cursor[d], 1);
    g_csrc[g_rowptr[d] + pos] = s;
}

// ---------------- tf32 HMMA GEMM: Tb[tile, NOUT] = H @ W ----------------
__device__ __forceinline__ void mma1688(float* d, uint32_t a0, uint32_t a1,
                                        uint32_t a2, uint32_t a3,
                                        uint32_t b0, uint32_t b1) {
    asm volatile(
        "mma.sync.aligned.m16n8k8.row.col.f32.tf32.tf32.f32 "
        "{%0,%1,%2,%3}, {%4,%5,%6,%7}, {%8,%9}, {%0,%1,%2,%3};"
        : "+f"(d[0]), "+f"(d[1]), "+f"(d[2]), "+f"(d[3])
        : "r"(a0), "r"(a1), "r"(a2), "r"(a3), "r"(b0), "r"(b1));
}

// 128 rows per CTA, 256 threads (8 warps). W transposed+tf32'd during staging.
template <int NOUT, int KIN>
__global__ void k_hmma(const float* __restrict__ Xin, int use_x,
                       const float* __restrict__ Wg, int N) {
    constexpr int S = KIN + 4;  // padded fp32 stride; frag LDS conflict-free
    constexpr int MI = (NOUT == 128) ? 2 : 1;
    constexpr int NI = (NOUT == 32) ? 4 : 8;
    extern __shared__ float smf[];
    float* Hs = smf;             // [128, S] (tf32 bits)
    float* Ws = smf + 128 * S;   // [NOUT, S] (tf32 bits, W^T)

    const float* __restrict__ Hin = use_x ? Xin : g_H;
    const int tid = threadIdx.x, wid = tid >> 5, lane = tid & 31;
    const int g = lane >> 2, tq = lane & 3;
    const int node0 = blockIdx.x * 128;
    const int rows0 = (NOUT == 128) ? (wid >> 1) * 32 : wid * 16;
    const int col0 = (NOUT == 128) ? (wid & 1) * 64 : 0;

    // stage A (fp32 -> tf32 bits)
    for (int idx = tid; idx < 128 * (KIN / 4); idx += 256) {
        int row = idx / (KIN / 4), c4 = (idx % (KIN / 4)) * 4;
        float4 v = make_float4(0.f, 0.f, 0.f, 0.f);
        int grow = node0 + row;
        if (grow < N) v = *(const float4*)&Hin[(size_t)grow * KIN + c4];
        uint4 t = make_uint4(f2tf32(v.x), f2tf32(v.y), f2tf32(v.z), f2tf32(v.w));
        *(uint4*)&Hs[row * S + c4] = t;
    }
    // stage W transposed: Ws[n*S+k] = tf32(W[k*NOUT+n]); coalesced reads over n
    for (int idx = tid; idx < KIN * (NOUT / 4); idx += 256) {
        int k = idx / (NOUT / 4), n4 = (idx % (NOUT / 4)) * 4;
        float4 w = *(const float4*)&Wg[(size_t)k * NOUT + n4];
        Ws[(n4 + 0) * S + k] = __uint_as_float(f2tf32(w.x));
        Ws[(n4 + 1) * S + k] = __uint_as_float(f2tf32(w.y));
        Ws[(n4 + 2) * S + k] = __uint_as_float(f2tf32(w.z));
        Ws[(n4 + 3) * S + k] = __uint_as_float(f2tf32(w.w));
    }
    __syncthreads();

    float acc[MI][NI][4];
#pragma unroll
    for (int mi = 0; mi < MI; mi++)
#pragma unroll
        for (int ni = 0; ni < NI; ni++)
#pragma unroll
            for (int i = 0; i < 4; i++) acc[mi][ni][i] = 0.f;

#pragma unroll
    for (int k0 = 0; k0 < KIN; k0 += 8) {
        uint32_t b0[NI], b1[NI];
#pragma unroll
        for (int ni = 0; ni < NI; ni++) {
            const float* wp = &Ws[(col0 + ni * 8 + g) * S + k0 + tq];
            b0[ni] = *(const uint32_t*)wp;
            b1[ni] = *(const uint32_t*)(wp + 4);
        }
#pragma unroll
        for (int mi = 0; mi < MI; mi++) {
            const float* ap = &Hs[(rows0 + mi * 16 + g) * S + k0 + tq];
            uint32_t a0 = *(const uint32_t*)ap;
            uint32_t a1 = *(const uint32_t*)(ap + 8 * S);
            uint32_t a2 = *(const uint32_t*)(ap + 4);
            uint32_t a3 = *(const uint32_t*)(ap + 8 * S + 4);
#pragma unroll
            for (int ni = 0; ni < NI; ni++)
                mma1688(acc[mi][ni], a0, a1, a2, a3, b0[ni], b1[ni]);
        }
    }

    // epilogue: bf16 pack, 32-bit stores (c0,c1) row g, (c2,c3) row g+8
#pragma unroll
    for (int mi = 0; mi < MI; mi++) {
        int r0 = node0 + rows0 + mi * 16 + g;
        int r1 = r0 + 8;
#pragma unroll
        for (int ni = 0; ni < NI; ni++) {
            int col = col0 + ni * 8 + tq * 2;
            if (r0 < N) {
                __nv_bfloat162 p = __floats2bfloat162_rn(acc[mi][ni][0], acc[mi][ni][1]);
                *(uint32_t*)&g_Tb[(size_t)r0 * NOUT + col] = *(uint32_t*)&p;
            }
            if (r1 < N) {
                __nv_bfloat162 p = __floats2bfloat162_rn(acc[mi][ni][2], acc[mi][ni][3]);
                *(uint32_t*)&g_Tb[(size_t)r1 * NOUT + col] = *(uint32_t*)&p;
            }
        }
    }
}

// ---------------- fused aggregation: H = relu(dinv^2*Tb + gather + b) ------
// CH = F/8 threads per node; each thread owns 8 bf16 cols (one uint4 load).
__device__ __forceinline__ void ld_bf8(const __nv_bfloat16* p, float* f) {
    uint4 u = *(const uint4*)p;
    float2 a = __bfloat1622float2(*reinterpret_cast<__nv_bfloat162*>(&u.x));
    float2 b = __bfloat1622float2(*reinterpret_cast<__nv_bfloat162*>(&u.y));
    float2 c = __bfloat1622float2(*reinterpret_cast<__nv_bfloat162*>(&u.z));
    float2 d = __bfloat1622float2(*reinterpret_cast<__nv_bfloat162*>(&u.w));
    f[0] = a.x; f[1] = a.y; f[2] = b.x; f[3] = b.y;
    f[4] = c.x; f[5] = c.y; f[6] = d.x; f[7] = d.y;
}

template <int CH>  // CH = F/8
__global__ void k_agg(const float* __restrict__ bias, int N) {
    constexpr int F = CH * 8;
    const int nodesPerBlk = blockDim.x / CH;
    const int grp = threadIdx.x / CH;
    const int c = threadIdx.x % CH;
    const int node = blockIdx.x * nodesPerBlk + grp;
    if (node >= N) return;

    int j = g_rowptr[node];
    const int jend = g_rowptr[node + 1];
    const float dv = g_dinv[node];

    float acc[8], v[8];
    ld_bf8(&g_Tb[(size_t)node * F + c * 8], acc);
    const float sl = dv * dv;
#pragma unroll
    for (int i = 0; i < 8; i++) acc[i] *= sl;

    for (; j + 4 <= jend; j += 4) {
        int s0 = g_csrc[j], s1 = g_csrc[j + 1], s2 = g_csrc[j + 2], s3 = g_csrc[j + 3];
        float n0 = g_dinv[s0] * dv, n1 = g_dinv[s1] * dv;
        float n2 = g_dinv[s2] * dv, n3 = g_dinv[s3] * dv;
        ld_bf8(&g_Tb[(size_t)s0 * F + c * 8], v);
#pragma unroll
        for (int i = 0; i < 8; i++) acc[i] = fmaf(n0, v[i], acc[i]);
        ld_bf8(&g_Tb[(size_t)s1 * F + c * 8], v);
#pragma unroll
        for (int i = 0; i < 8; i++) acc[i] = fmaf(n1, v[i], acc[i]);
        ld_bf8(&g_Tb[(size_t)s2 * F + c * 8], v);
#pragma unroll
        for (int i = 0; i < 8; i++) acc[i] = fmaf(n2, v[i], acc[i]);
        ld_bf8(&g_Tb[(size_t)s3 * F + c * 8], v);
#pragma unroll
        for (int i = 0; i < 8; i++) acc[i] = fmaf(n3, v[i], acc[i]);
    }
    for (; j < jend; j++) {
        int s = g_csrc[j];
        float nn = g_dinv[s] * dv;
        ld_bf8(&g_Tb[(size_t)s * F + c * 8], v);
#pragma unroll
        for (int i = 0; i < 8; i++) acc[i] = fmaf(nn, v[i], acc[i]);
    }

    float4 b0 = ((const float4*)bias)[c * 2];
    float4 b1 = ((const float4*)bias)[c * 2 + 1];
    acc[0] = fmaxf(acc[0] + b0.x, 0.f); acc[1] = fmaxf(acc[1] + b0.y, 0.f);
    acc[2] = fmaxf(acc[2] + b0.z, 0.f); acc[3] = fmaxf(acc[3] + b0.w, 0.f);
    acc[4] = fmaxf(acc[4] + b1.x, 0.f); acc[5] = fmaxf(acc[5] + b1.y, 0.f);
    acc[6] = fmaxf(acc[6] + b1.z, 0.f); acc[7] = fmaxf(acc[7] + b1.w, 0.f);
    float* dst = &g_H[(size_t)node * F + c * 8];
    *(float4*)dst = make_float4(acc[0], acc[1], acc[2], acc[3]);
    *(float4*)(dst + 4) = make_float4(acc[4], acc[5], acc[6], acc[7]);
}

// ---------------- pooling + FC ----------------
__global__ void k_zero_pool() {
    int i = blockIdx.x * blockDim.x + threadIdx.x;
    if (i < NGRAPH * 32) g_pool[i] = 0.0f;
    if (i < NGRAPH) g_cnt[i] = 0.0f;
}

__global__ void k_pool(const int* __restrict__ batch, int N) {
    int warp = (blockIdx.x * blockDim.x + threadIdx.x) >> 5;
    int lane = threadIdx.x & 31;
    int i0 = warp * 32;
    if (i0 >= N) return;
    int iend = min(i0 + 32, N);

    int curg = batch[i0];
    float acc = 0.0f, cnt = 0.0f;
    for (int i = i0; i < iend; i++) {
        int g = batch[i];
        if (g != curg) {
            atomicAdd(&g_pool[curg * 32 + lane], acc);
            if (lane == 0) atomicAdd(&g_cnt[curg], cnt);
            acc = 0.0f; cnt = 0.0f; curg = g;
        }
        acc += g_H[(size_t)i * 32 + lane];
        cnt += 1.0f;
    }
    atomicAdd(&g_pool[curg * 32 + lane], acc);
    if (lane == 0) atomicAdd(&g_cnt[curg], cnt);
}

__global__ void k_fc(const float* __restrict__ Wfc, const float* __restrict__ bfc,
                     float* __restrict__ out) {
    int t = threadIdx.x;
    if (t >= NGRAPH * 10) return;
    int g = t / 10, o = t % 10;
    float inv = 1.0f / fmaxf(g_cnt[g], 1.0f);
    float s = bfc[o];
#pragma unroll
    for (int k = 0; k < 32; k++) s = fmaf(g_pool[g * 32 + k] * inv, Wfc[k * 10 + o], s);
    out[g * 10 + o] = s;
}

// ---------------------------------------------------------------------------
extern "C" void kernel_launch(void* const* d_in, const int* in_sizes, int n_in,
                              void* d_out, int out_size) {
    const float* x = (const float*)d_in[0];
    const int* ei = (const int*)d_in[1];
    const int* batch = (const int*)d_in[2];
    const float* W[5] = {(const float*)d_in[3], (const float*)d_in[5],
                         (const float*)d_in[7], (const float*)d_in[9],
                         (const float*)d_in[11]};
    const float* b[5] = {(const float*)d_in[4], (const float*)d_in[6],
                         (const float*)d_in[8], (const float*)d_in[10],
                         (const float*)d_in[12]};
    const float* Wfc = (const float*)d_in[13];
    const float* bfc = (const float*)d_in[14];
    float* out = (float*)d_out;

    int N = in_sizes[0] / 128;
    int E = in_sizes[1] / 2;
    int nb = (N + SCAN_BLK - 1) / SCAN_BLK;

    // dynamic smem: (128 + NOUT) * (KIN+4) * 4 bytes
    const int smem128 = (128 + 128) * 132 * 4;  // 135168
    const int smem64 = (128 + 64) * 132 * 4;    // 101376
    const int smem32 = (128 + 32) * 68 * 4;     // 43520
    cudaFuncSetAttribute(k_hmma<128, 128>, cudaFuncAttributeMaxDynamicSharedMemorySize, smem128);
    cudaFuncSetAttribute(k_hmma<64, 128>, cudaFuncAttributeMaxDynamicSharedMemorySize, smem64);
    cudaFuncSetAttribute(k_hmma<32, 64>, cudaFuncAttributeMaxDynamicSharedMemorySize, smem32);

    // CSR build (dinv fused into scan1; fill writes csrc only)
    k_zero_cnt<<<(N + 255) / 256, 256>>>(N);
    k_count<<<(E + 255) / 256, 256>>>(ei, E);
    k_scan1<<<nb, SCAN_BLK>>>(N);
    k_scan2<<<1, 512>>>(nb);
    k_scan3<<<nb, SCAN_BLK>>>(N);
    k_fill<<<(E + 255) / 256, 256>>>(ei, E);

    int gridT = (N + 127) / 128;
    // L1..L3: 128->128
    for (int l = 0; l < 3; l++) {
        k_hmma<128, 128><<<gridT, 256, smem128>>>(x, l == 0 ? 1 : 0, W[l], N);
        k_agg<16><<<(N + 15) / 16, 256>>>(b[l], N);
    }
    // L4: 128->64
    k_hmma<64, 128><<<gridT, 256, smem64>>>(x, 0, W[3], N);
    k_agg<8><<<(N + 31) / 32, 256>>>(b[3], N);
    // L5: 64->32
    k_hmma<32, 64><<<gridT, 256, smem32>>>(x, 0, W[4], N);
    k_agg<4><<<(N + 63) / 64, 256>>>(b[4], N);

    k_zero_pool<<<(NGRAPH * 32 + 255) / 256, 256>>>();
    k_pool<<<(N + 255) / 256, 256>>>(batch, N);
    k_fc<<<1, NGRAPH * 10>>>(Wfc, bfc, out);
}

// round 13
// speedup vs baseline: 1.0513x; 1.0513x over previous
#include <cuda_runtime.h>
#include <cuda_bf16.h>
#include <cstdint>

// ---------------------------------------------------------------------------
// GCN5 — R11: R8 GEMM path (separate k_wt, conflict-free staging) + 16B bf16
// gathers with restored MLP=4 (independent v0..v3) in k_agg.
//   Tb = bf16(H @ W)    (128-node tile, 8 warps, m16n8k8 tf32 MMA)
//   H  = relu(dinv^2*Tb + sum_in dinv[s]*dinv[d]*Tb[s] + b)   (fp32 accum)
// ---------------------------------------------------------------------------

#define MAXN 100000
#define MAXE 1600000
#define MAXF 128
#define NGRAPH 64
#define SCAN_BLK 256

__device__ __align__(16) __nv_bfloat16 g_Tb[MAXN * MAXF];  // post-GEMM (bf16)
__device__ float g_H[MAXN * MAXF];       // activations (fp32)
__device__ float g_Wt[MAXF * MAXF];      // W^T, tf32 bits (K-major)
__device__ float g_dinv[MAXN];
__device__ int   g_cnt_i[MAXN];
__device__ int   g_rowptr[MAXN + 1];
__device__ int   g_cursor[MAXN];
__device__ int   g_csrc[MAXE];
__device__ int   g_bsum[512];
__device__ float g_pool[NGRAPH * 32];
__device__ float g_cnt[NGRAPH];

__device__ __forceinline__ uint32_t f2tf32(float f) {
    uint32_t r;
    asm("cvt.rna.tf32.f32 %0, %1;" : "=r"(r) : "f"(f));
    return r;
}

// ---------------- CSR build ----------------
__global__ void k_zero_cnt(int N) {
    int i = blockIdx.x * blockDim.x + threadIdx.x;
    if (i < N) g_cnt_i[i] = 0;
}
__global__ void k_count(const int* __restrict__ ei, int E) {
    int e = blockIdx.x * blockDim.x + threadIdx.x;
    if (e < E) atomicAdd(&g_cnt_i[ei[E + e]], 1);
}
// scan1 also computes dinv (deg = cnt + 1 self loop) and zeroes cursors.
__global__ void k_scan1(int N) {
    __shared__ int sh[SCAN_BLK];
    int tid = threadIdx.x;
    int i = blockIdx.x * SCAN_BLK + tid;
    int cnt = (i < N) ? g_cnt_i[i] : 0;
    if (i < N) {
        g_dinv[i] = rsqrtf((float)cnt + 1.0f);
        g_cursor[i] = 0;
    }
    sh[tid] = cnt;
    __syncthreads();
#pragma unroll
    for (int o = 1; o < SCAN_BLK; o <<= 1) {
        int t = (tid >= o) ? sh[tid - o] : 0;
        __syncthreads();
        sh[tid] += t;
        __syncthreads();
    }
    if (i < N) g_rowptr[i + 1] = sh[tid];
    if (tid == SCAN_BLK - 1) g_bsum[blockIdx.x] = sh[tid];
}
__global__ void k_scan2(int nb) {
    __shared__ int sh[512];
    int tid = threadIdx.x;
    sh[tid] = (tid < nb) ? g_bsum[tid] : 0;
    __syncthreads();
#pragma unroll
    for (int o = 1; o < 512; o <<= 1) {
        int t = (tid >= o) ? sh[tid - o] : 0;
        __syncthreads();
        sh[tid] += t;
        __syncthreads();
    }
    if (tid < nb) g_bsum[tid] = sh[tid];
}
__global__ void k_scan3(int N) {
    int i = blockIdx.x * SCAN_BLK + threadIdx.x;
    if (i < N && blockIdx.x > 0) g_rowptr[i + 1] += g_bsum[blockIdx.x - 1];
    if (i == 0) g_rowptr[0] = 0;
}
__global__ void k_fill(const int* __restrict__ ei, int E) {
    int e = blockIdx.x * blockDim.x + threadIdx.x;
    if (e >= E) return;
    int s = ei[e];
    int d = ei[E + e];
    int pos = atomicAdd(&g_cursor[d], 1);
    g_csrc[g_rowptr[d] + pos] = s;
}

// ---------------- weight prep: g_Wt[n*KIN+k] = tf32(W[k*NOUT+n]) ----------
__global__ void k_wt(const float* __restrict__ W, int NOUT, int KIN) {
    int idx = blockIdx.x * blockDim.x + threadIdx.x;
    if (idx >= NOUT * KIN) return;
    int n = idx / KIN, k = idx % KIN;
    g_Wt[idx] = __uint_as_float(f2tf32(W[k * NOUT + n]));
}

// ---------------- tf32 HMMA GEMM: Tb[tile, NOUT] = H @ W ----------------
__device__ __forceinline__ void mma1688(float* d, uint32_t a0, uint32_t a1,
                                        uint32_t a2, uint32_t a3,
                                        uint32_t b0, uint32_t b1) {
    asm volatile(
        "mma.sync.aligned.m16n8k8.row.col.f32.tf32.tf32.f32 "
        "{%0,%1,%2,%3}, {%4,%5,%6,%7}, {%8,%9}, {%0,%1,%2,%3};"
        : "+f"(d[0]), "+f"(d[1]), "+f"(d[2]), "+f"(d[3])
        : "r"(a0), "r"(a1), "r"(a2), "r"(a3), "r"(b0), "r"(b1));
}

// 128 rows per CTA, 256 threads (8 warps).
template <int NOUT, int KIN>
__global__ void k_hmma(const float* __restrict__ Xin, int use_x, int N) {
    constexpr int S = KIN + 4;  // padded fp32 stride; frag LDS conflict-free
    constexpr int MI = (NOUT == 128) ? 2 : 1;
    constexpr int NI = (NOUT == 32) ? 4 : 8;
    extern __shared__ float smf[];
    float* Hs = smf;             // [128, S] (tf32 bits)
    float* Ws = smf + 128 * S;   // [NOUT, S] (tf32 bits)

    const float* __restrict__ Hin = use_x ? Xin : g_H;
    const int tid = threadIdx.x, wid = tid >> 5, lane = tid & 31;
    const int g = lane >> 2, tq = lane & 3;
    const int node0 = blockIdx.x * 128;
    const int rows0 = (NOUT == 128) ? (wid >> 1) * 32 : wid * 16;
    const int col0 = (NOUT == 128) ? (wid & 1) * 64 : 0;

    // stage A (fp32 -> tf32 bits)
    for (int idx = tid; idx < 128 * (KIN / 4); idx += 256) {
        int row = idx / (KIN / 4), c4 = (idx % (KIN / 4)) * 4;
        float4 v = make_float4(0.f, 0.f, 0.f, 0.f);
        int grow = node0 + row;
        if (grow < N) v = *(const float4*)&Hin[(size_t)grow * KIN + c4];
        uint4 t = make_uint4(f2tf32(v.x), f2tf32(v.y), f2tf32(v.z), f2tf32(v.w));
        *(uint4*)&Hs[row * S + c4] = t;
    }
    // stage W (already transposed + tf32)
    for (int idx = tid; idx < NOUT * (KIN / 4); idx += 256) {
        int row = idx / (KIN / 4), c4 = (idx % (KIN / 4)) * 4;
        *(float4*)&Ws[row * S + c4] = *(const float4*)&g_Wt[(size_t)row * KIN + c4];
    }
    __syncthreads();

    float acc[MI][NI][4];
#pragma unroll
    for (int mi = 0; mi < MI; mi++)
#pragma unroll
        for (int ni = 0; ni < NI; ni++)
#pragma unroll
            for (int i = 0; i < 4; i++) acc[mi][ni][i] = 0.f;

#pragma unroll
    for (int k0 = 0; k0 < KIN; k0 += 8) {
        uint32_t b0[NI], b1[NI];
#pragma unroll
        for (int ni = 0; ni < NI; ni++) {
            const float* wp = &Ws[(col0 + ni * 8 + g) * S + k0 + tq];
            b0[ni] = *(const uint32_t*)wp;
            b1[ni] = *(const uint32_t*)(wp + 4);
        }
#pragma unroll
        for (int mi = 0; mi < MI; mi++) {
            const float* ap = &Hs[(rows0 + mi * 16 + g) * S + k0 + tq];
            uint32_t a0 = *(const uint32_t*)ap;
            uint32_t a1 = *(const uint32_t*)(ap + 8 * S);
            uint32_t a2 = *(const uint32_t*)(ap + 4);
            uint32_t a3 = *(const uint32_t*)(ap + 8 * S + 4);
#pragma unroll
            for (int ni = 0; ni < NI; ni++)
                mma1688(acc[mi][ni], a0, a1, a2, a3, b0[ni], b1[ni]);
        }
    }

    // epilogue: bf16 pack, 32-bit stores (c0,c1) row g, (c2,c3) row g+8
#pragma unroll
    for (int mi = 0; mi < MI; mi++) {
        int r0 = node0 + rows0 + mi * 16 + g;
        int r1 = r0 + 8;
#pragma unroll
        for (int ni = 0; ni < NI; ni++) {
            int col = col0 + ni * 8 + tq * 2;
            if (r0 < N) {
                __nv_bfloat162 p = __floats2bfloat162_rn(acc[mi][ni][0], acc[mi][ni][1]);
                *(uint32_t*)&g_Tb[(size_t)r0 * NOUT + col] = *(uint32_t*)&p;
            }
            if (r1 < N) {
                __nv_bfloat162 p = __floats2bfloat162_rn(acc[mi][ni][2], acc[mi][ni][3]);
                *(uint32_t*)&g_Tb[(size_t)r1 * NOUT + col] = *(uint32_t*)&p;
            }
        }
    }
}

// ---------------- fused aggregation: H = relu(dinv^2*Tb + gather + b) ------
// CH = F/8 threads per node; 16B loads; 4 independent in-flight gathers.
__device__ __forceinline__ void ld_bf8(const __nv_bfloat16* p, float* f) {
    uint4 u = *(const uint4*)p;
    float2 a = __bfloat1622float2(*reinterpret_cast<__nv_bfloat162*>(&u.x));
    float2 b = __bfloat1622float2(*reinterpret_cast<__nv_bfloat162*>(&u.y));
    float2 c = __bfloat1622float2(*reinterpret_cast<__nv_bfloat162*>(&u.z));
    float2 d = __bfloat1622float2(*reinterpret_cast<__nv_bfloat162*>(&u.w));
    f[0] = a.x; f[1] = a.y; f[2] = b.x; f[3] = b.y;
    f[4] = c.x; f[5] = c.y; f[6] = d.x; f[7] = d.y;
}

template <int CH>  // CH = F/8
__global__ void k_agg(const float* __restrict__ bias, int N) {
    constexpr int F = CH * 8;
    const int nodesPerBlk = blockDim.x / CH;
    const int grp = threadIdx.x / CH;
    const int c = threadIdx.x % CH;
    const int node = blockIdx.x * nodesPerBlk + grp;
    if (node >= N) return;

    int j = g_rowptr[node];
    const int jend = g_rowptr[node + 1];
    const float dv = g_dinv[node];

    float acc[8];
    ld_bf8(&g_Tb[(size_t)node * F + c * 8], acc);
    const float sl = dv * dv;
#pragma unroll
    for (int i = 0; i < 8; i++) acc[i] *= sl;

    for (; j + 4 <= jend; j += 4) {
        // batch index + norm loads first, then 4 independent 16B gathers
        int s0 = g_csrc[j], s1 = g_csrc[j + 1], s2 = g_csrc[j + 2], s3 = g_csrc[j + 3];
        float n0 = g_dinv[s0] * dv, n1 = g_dinv[s1] * dv;
        float n2 = g_dinv[s2] * dv, n3 = g_dinv[s3] * dv;
        float v0[8], v1[8], v2[8], v3[8];
        ld_bf8(&g_Tb[(size_t)s0 * F + c * 8], v0);
        ld_bf8(&g_Tb[(size_t)s1 * F + c * 8], v1);
        ld_bf8(&g_Tb[(size_t)s2 * F + c * 8], v2);
        ld_bf8(&g_Tb[(size_t)s3 * F + c * 8], v3);
#pragma unroll
        for (int i = 0; i < 8; i++) acc[i] = fmaf(n0, v0[i], acc[i]);
#pragma unroll
        for (int i = 0; i < 8; i++) acc[i] = fmaf(n1, v1[i], acc[i]);
#pragma unroll
        for (int i = 0; i < 8; i++) acc[i] = fmaf(n2, v2[i], acc[i]);
#pragma unroll
        for (int i = 0; i < 8; i++) acc[i] = fmaf(n3, v3[i], acc[i]);
    }
    for (; j < jend; j++) {
        int s = g_csrc[j];
        float nn = g_dinv[s] * dv;
        float v[8];
        ld_bf8(&g_Tb[(size_t)s * F + c * 8], v);
#pragma unroll
        for (int i = 0; i < 8; i++) acc[i] = fmaf(nn, v[i], acc[i]);
    }

    float4 b0 = ((const float4*)bias)[c * 2];
    float4 b1 = ((const float4*)bias)[c * 2 + 1];
    acc[0] = fmaxf(acc[0] + b0.x, 0.f); acc[1] = fmaxf(acc[1] + b0.y, 0.f);
    acc[2] = fmaxf(acc[2] + b0.z, 0.f); acc[3] = fmaxf(acc[3] + b0.w, 0.f);
    acc[4] = fmaxf(acc[4] + b1.x, 0.f); acc[5] = fmaxf(acc[5] + b1.y, 0.f);
    acc[6] = fmaxf(acc[6] + b1.z, 0.f); acc[7] = fmaxf(acc[7] + b1.w, 0.f);
    float* dst = &g_H[(size_t)node * F + c * 8];
    *(float4*)dst = make_float4(acc[0], acc[1], acc[2], acc[3]);
    *(float4*)(dst + 4) = make_float4(acc[4], acc[5], acc[6], acc[7]);
}

// ---------------- pooling + FC ----------------
__global__ void k_zero_pool() {
    int i = blockIdx.x * blockDim.x + threadIdx.x;
    if (i < NGRAPH * 32) g_pool[i] = 0.0f;
    if (i < NGRAPH) g_cnt[i] = 0.0f;
}

__global__ void k_pool(const int* __restrict__ batch, int N) {
    int warp = (blockIdx.x * blockDim.x + threadIdx.x) >> 5;
    int lane = threadIdx.x & 31;
    int i0 = warp * 32;
    if (i0 >= N) return;
    int iend = min(i0 + 32, N);

    int curg = batch[i0];
    float acc = 0.0f, cnt = 0.0f;
    for (int i = i0; i < iend; i++) {
        int g = batch[i];
        if (g != curg) {
            atomicAdd(&g_pool[curg * 32 + lane], acc);
            if (lane == 0) atomicAdd(&g_cnt[curg], cnt);
            acc = 0.0f; cnt = 0.0f; curg = g;
        }
        acc += g_H[(size_t)i * 32 + lane];
        cnt += 1.0f;
    }
    atomicAdd(&g_pool[curg * 32 + lane], acc);
    if (lane == 0) atomicAdd(&g_cnt[curg], cnt);
}

__global__ void k_fc(const float* __restrict__ Wfc, const float* __restrict__ bfc,
                     float* __restrict__ out) {
    int t = threadIdx.x;
    if (t >= NGRAPH * 10) return;
    int g = t / 10, o = t % 10;
    float inv = 1.0f / fmaxf(g_cnt[g], 1.0f);
    float s = bfc[o];
#pragma unroll
    for (int k = 0; k < 32; k++) s = fmaf(g_pool[g * 32 + k] * inv, Wfc[k * 10 + o], s);
    out[g * 10 + o] = s;
}

// ---------------------------------------------------------------------------
extern "C" void kernel_launch(void* const* d_in, const int* in_sizes, int n_in,
                              void* d_out, int out_size) {
    const float* x = (const float*)d_in[0];
    const int* ei = (const int*)d_in[1];
    const int* batch = (const int*)d_in[2];
    const float* W[5] = {(const float*)d_in[3], (const float*)d_in[5],
                         (const float*)d_in[7], (const float*)d_in[9],
                         (const float*)d_in[11]};
    const float* b[5] = {(const float*)d_in[4], (const float*)d_in[6],
                         (const float*)d_in[8], (const float*)d_in[10],
                         (const float*)d_in[12]};
    const float* Wfc = (const float*)d_in[13];
    const float* bfc = (const float*)d_in[14];
    float* out = (float*)d_out;

    int N = in_sizes[0] / 128;
    int E = in_sizes[1] / 2;
    int nb = (N + SCAN_BLK - 1) / SCAN_BLK;

    // dynamic smem: (128 + NOUT) * (KIN+4) * 4 bytes
    const int smem128 = (128 + 128) * 132 * 4;  // 135168
    const int smem64 = (128 + 64) * 132 * 4;    // 101376
    const int smem32 = (128 + 32) * 68 * 4;     // 43520
    cudaFuncSetAttribute(k_hmma<128, 128>, cudaFuncAttributeMaxDynamicSharedMemorySize, smem128);
    cudaFuncSetAttribute(k_hmma<64, 128>, cudaFuncAttributeMaxDynamicSharedMemorySize, smem64);
    cudaFuncSetAttribute(k_hmma<32, 64>, cudaFuncAttributeMaxDynamicSharedMemorySize, smem32);

    // CSR build (dinv fused into scan1; fill writes csrc only)
    k_zero_cnt<<<(N + 255) / 256, 256>>>(N);
    k_count<<<(E + 255) / 256, 256>>>(ei, E);
    k_scan1<<<nb, SCAN_BLK>>>(N);
    k_scan2<<<1, 512>>>(nb);
    k_scan3<<<nb, SCAN_BLK>>>(N);
    k_fill<<<(E + 255) / 256, 256>>>(ei, E);

    int gridT = (N + 127) / 128;
    // L1..L3: 128->128
    for (int l = 0; l < 3; l++) {
        k_wt<<<(128 * 128 + 255) / 256, 256>>>(W[l], 128, 128);
        k_hmma<128, 128><<<gridT, 256, smem128>>>(x, l == 0 ? 1 : 0, N);
        k_agg<16><<<(N + 15) / 16, 256>>>(b[l], N);
    }
    // L4: 128->64
    k_wt<<<(64 * 128 + 255) / 256, 256>>>(W[3], 64, 128);
    k_hmma<64, 128><<<gridT, 256, smem64>>>(x, 0, N);
    k_agg<8><<<(N + 31) / 32, 256>>>(b[3], N);
    // L5: 64->32
    k_wt<<<(32 * 64 + 255) / 256, 256>>>(W[4], 32, 64);
    k_hmma<32, 64><<<gridT, 256, smem32>>>(x, 0, N);
    k_agg<4><<<(N + 63) / 64, 256>>>(b[4], N);

    k_zero_pool<<<(NGRAPH * 32 + 255) / 256, 256>>>();
    k_pool<<<(N + 255) / 256, 256>>>(batch, N);
    k_fc<<<1, NGRAPH * 10>>>(Wfc, bfc, out);
}